// round 6
// baseline (speedup 1.0000x reference)
#include <cuda_runtime.h>
#include <cuda_bf16.h>
#include <cstdint>

#define NP   1000000
#define KSEG 30
#define H    128

#define WTILES (NP / 16)      // 62500 warp-tiles of 16 points
#define GRID_MMA 304
#define WARPS_PER_BLK 8

typedef unsigned int uint;

// ---------------- scratch (device globals; no allocation allowed) ----------
__device__ unsigned g_umax[KSEG * 3];
__device__ unsigned g_umin[KSEG * 3];
__device__ float    g_xc[KSEG * 3];
__device__ int      g_ind[NP];

__device__ __forceinline__ unsigned fenc(float f) {
    unsigned u = __float_as_uint(f);
    return (u & 0x80000000u) ? ~u : (u | 0x80000000u);
}
__device__ __forceinline__ float fdec(unsigned k) {
    unsigned u = (k & 0x80000000u) ? (k & 0x7FFFFFFFu) : ~k;
    return __uint_as_float(u);
}

// ---------------- small PTX helpers (all baseline features) ----------------
__device__ __forceinline__ uint smem_u32(const void* p) {
    uint a;
    asm("{ .reg .u64 t; cvta.to.shared.u64 t, %1; cvt.u32.u64 %0, t; }"
        : "=r"(a) : "l"(p));
    return a;
}
// pack two fp32 into bf16x2: reg.lo = c0, reg.hi = c1
__device__ __forceinline__ uint pack_bf16x2(float c0, float c1) {
    uint r;
    asm("cvt.rn.bf16x2.f32 %0, %1, %2;" : "=r"(r) : "f"(c1), "f"(c0));
    return r;
}
__device__ __forceinline__ float bf16_round(float v) {
    return __bfloat162float(__float2bfloat16_rn(v));
}
// x4 trans ldmatrix: lanes 0-15 -> n-chunk c0 rows, lanes 16-31 -> chunk c1
// -> r0,r1 = c0 k0-7,k8-15 ; r2,r3 = c1 k0-7,k8-15
__device__ __forceinline__ void ldsm_x4_t(uint& r0, uint& r1, uint& r2, uint& r3,
                                          uint addr) {
    asm volatile("ldmatrix.sync.aligned.m8n8.x4.trans.shared.b16 {%0,%1,%2,%3}, [%4];"
                 : "=r"(r0), "=r"(r1), "=r"(r2), "=r"(r3) : "r"(addr));
}
__device__ __forceinline__ void mma16816(float* d,
                                         const uint* a,
                                         uint b0, uint b1) {
    asm volatile("mma.sync.aligned.m16n8k16.row.col.f32.bf16.bf16.f32 "
                 "{%0,%1,%2,%3}, {%4,%5,%6,%7}, {%8,%9}, {%0,%1,%2,%3};"
                 : "+f"(d[0]), "+f"(d[1]), "+f"(d[2]), "+f"(d[3])
                 : "r"(a[0]), "r"(a[1]), "r"(a[2]), "r"(a[3]), "r"(b0), "r"(b1));
}

// ---------------- kernel 0: reset reduction scratch ------------------------
__global__ void k_init() {
    int t = threadIdx.x;
    if (t < KSEG * 3) { g_umax[t] = 0u; g_umin[t] = 0xFFFFFFFFu; }
}

// ---------------- kernel 1: cluster centers (after fused kernel) -----------
__global__ void k_centers() {
    int t = threadIdx.x;
    if (t < KSEG * 3) g_xc[t] = 0.5f * (fdec(g_umax[t]) + fdec(g_umin[t]));
}

// ---------------- fused kernel: softmax+argmax+segmax + MLP (mma.sync) -----
// smem byte layout:
//   [0)      Bhi : 128 x 136 bf16  (34816)  row stride 272 B
//   [34816)  Blo : 128 x 136 bf16  (34816)
//   [69632)  W14 : 128 float4 (w1x,w1y,w1z,b1)   (2048)
//   [71680)  b2s : 128 f32   (512)
//   [72192)  W3s : 512 f32   (2048)
//   [74240)  b3s : 4 f32     (16)
//   [74256)  umax: 90 u32    (360)
//   [74616)  umin: 90 u32    (360)
//   [74976)  buf : 8 warps x 496 f32  (15872)   (480 logits + 16 sinv)
#define OFF_BHI 0
#define OFF_BLO 34816
#define OFF_W14 69632
#define OFF_B2  71680
#define OFF_W3  72192
#define OFF_B3  74240
#define OFF_UMX 74256
#define OFF_UMN 74616
#define OFF_BUF 74976
#define SM_TOTAL 90848
#define LDB 136   // bf16 elems per B row

__global__ void __launch_bounds__(256, 2)
k_fused(const float* __restrict__ pc1, const float* __restrict__ logits,
        const float* __restrict__ W1, const float* __restrict__ b1,
        const float* __restrict__ W2, const float* __restrict__ b2,
        const float* __restrict__ W3, const float* __restrict__ b3,
        float* __restrict__ out)
{
    extern __shared__ char smc[];
    __nv_bfloat16* BhiS = (__nv_bfloat16*)(smc + OFF_BHI);
    __nv_bfloat16* BloS = (__nv_bfloat16*)(smc + OFF_BLO);
    float4*   W14 = (float4*)(smc + OFF_W14);
    float*    b2s = (float*)(smc + OFF_B2);
    float*    W3s = (float*)(smc + OFF_W3);
    float*    b3s = (float*)(smc + OFF_B3);
    unsigned* umax = (unsigned*)(smc + OFF_UMX);
    unsigned* umin = (unsigned*)(smc + OFF_UMN);

    const int tid = threadIdx.x;

    // one-time weight staging
    for (int x = tid; x < H * H; x += 256) {
        int i = x >> 7, j = x & 127;
        float v  = W2[x];
        float hi = bf16_round(v);
        BhiS[i * LDB + j] = __float2bfloat16_rn(hi);
        BloS[i * LDB + j] = __float2bfloat16_rn(v - hi);
    }
    if (tid < 128) {
        W14[tid] = make_float4(W1[tid], W1[128 + tid], W1[256 + tid], b1[tid]);
        b2s[tid] = b2[tid];
    }
    for (int i = tid; i < 512; i += 256) W3s[i] = W3[i];
    if (tid < 4) b3s[tid] = b3[tid];
    if (tid < KSEG * 3) { umax[tid] = 0u; umin[tid] = 0xFFFFFFFFu; }
    __syncthreads();

    const int w  = tid >> 5;
    const int l  = tid & 31;
    const int lq = l & 3;     // quad id -> j columns
    const int lr = l >> 2;    // row group -> point rows

    float* wbuf = (float*)(smc + OFF_BUF) + w * 496;
    float* sinv = wbuf + 480;

    // ldmatrix lane base for n-PAIR loads:
    // lanes 0-15 -> chunk 2*np (col byte +0), lanes 16-31 -> chunk 2*np+1 (+16B)
    const uint bhi_b = smem_u32(BhiS) + (uint)(l & 15) * (LDB * 2)
                     + (uint)((l >> 4) & 1) * 16u;
    const uint blo_b = bhi_b + (uint)(OFF_BLO - OFF_BHI);

    float* outMask = out + (size_t)3  * NP;
    float* outT    = out + (size_t)33 * NP;
    float* outYaw  = out + (size_t)36 * NP;

    for (int wt = blockIdx.x * WARPS_PER_BLK + w; wt < WTILES;
         wt += GRID_MMA * WARPS_PER_BLK)
    {
        const int base = wt * 16;

        // ================= softmax + argmax + segment atomics ==============
        __syncwarp();   // protect wbuf/sinv reuse across iterations
        const float* lsrc = logits + (size_t)base * 30;
        #pragma unroll
        for (int r = 0; r < 15; r++) wbuf[r * 32 + l] = lsrc[r * 32 + l];
        __syncwarp();

        {
            int pl = l & 15, hf = l >> 4;
            float* my = wbuf + pl * 30 + hf * 15;
            float bv = my[0]; int bi = 0;
            #pragma unroll
            for (int k = 1; k < 15; k++) {
                float v = my[k];
                if (v > bv) { bv = v; bi = k; }
            }
            bi += hf * 15;
            float bvo = __shfl_xor_sync(0xFFFFFFFFu, bv, 16);
            int   bio = __shfl_xor_sync(0xFFFFFFFFu, bi, 16);
            if (bvo > bv || (bvo == bv && bio < bi)) { bv = bvo; bi = bio; }

            float acc = 0.f;
            #pragma unroll
            for (int k = 0; k < 15; k++) {
                float e = __expf(my[k] - bv);
                my[k] = e; acc += e;
            }
            acc += __shfl_xor_sync(0xFFFFFFFFu, acc, 16);

            if (hf == 0) {
                sinv[pl] = 1.0f / acc;
                int p = base + pl;
                g_ind[p] = bi;
                float qx = pc1[p * 3 + 0];
                float qy = pc1[p * 3 + 1];
                float qz = pc1[p * 3 + 2];
                atomicMax(&umax[bi * 3 + 0], fenc(qx));
                atomicMax(&umax[bi * 3 + 1], fenc(qy));
                atomicMax(&umax[bi * 3 + 2], fenc(qz));
                atomicMin(&umin[bi * 3 + 0], fenc(qx));
                atomicMin(&umin[bi * 3 + 1], fenc(qy));
                atomicMin(&umin[bi * 3 + 2], fenc(qz));
            }
        }
        __syncwarp();

        float* mdst = outMask + (size_t)base * 30;
        #pragma unroll
        for (int r = 0; r < 15; r++) {
            int j = r * 32 + l;
            mdst[j] = wbuf[j] * sinv[(j * 2185) >> 16];   // j/30 exact for j<480
        }

        // ================= layer 1 -> A fragments (hi/lo bf16 split) =======
        const int p0 = base + lr;
        const int p1 = p0 + 8;
        float x0 = pc1[p0 * 3 + 0], y0 = pc1[p0 * 3 + 1], z0 = pc1[p0 * 3 + 2];
        float x1 = pc1[p1 * 3 + 0], y1 = pc1[p1 * 3 + 1], z1 = pc1[p1 * 3 + 2];

        uint ahi[8][4], alo[8][4];
        #pragma unroll
        for (int kk = 0; kk < 8; kk++) {
            int ib = kk * 16 + lq * 2;
            float4 wv0 = W14[ib],     wv1 = W14[ib + 1];
            float4 wv8 = W14[ib + 8], wv9 = W14[ib + 9];
            float v00 = fmaxf(fmaf(x0, wv0.x, fmaf(y0, wv0.y, fmaf(z0, wv0.z, wv0.w))), 0.f);
            float v01 = fmaxf(fmaf(x0, wv1.x, fmaf(y0, wv1.y, fmaf(z0, wv1.z, wv1.w))), 0.f);
            float v02 = fmaxf(fmaf(x0, wv8.x, fmaf(y0, wv8.y, fmaf(z0, wv8.z, wv8.w))), 0.f);
            float v03 = fmaxf(fmaf(x0, wv9.x, fmaf(y0, wv9.y, fmaf(z0, wv9.z, wv9.w))), 0.f);
            float v10 = fmaxf(fmaf(x1, wv0.x, fmaf(y1, wv0.y, fmaf(z1, wv0.z, wv0.w))), 0.f);
            float v11 = fmaxf(fmaf(x1, wv1.x, fmaf(y1, wv1.y, fmaf(z1, wv1.z, wv1.w))), 0.f);
            float v12 = fmaxf(fmaf(x1, wv8.x, fmaf(y1, wv8.y, fmaf(z1, wv8.z, wv8.w))), 0.f);
            float v13 = fmaxf(fmaf(x1, wv9.x, fmaf(y1, wv9.y, fmaf(z1, wv9.z, wv9.w))), 0.f);

            float h00 = bf16_round(v00), h01 = bf16_round(v01);
            float h02 = bf16_round(v02), h03 = bf16_round(v03);
            float h10 = bf16_round(v10), h11 = bf16_round(v11);
            float h12 = bf16_round(v12), h13 = bf16_round(v13);
            ahi[kk][0] = pack_bf16x2(h00, h01);
            ahi[kk][1] = pack_bf16x2(h10, h11);
            ahi[kk][2] = pack_bf16x2(h02, h03);
            ahi[kk][3] = pack_bf16x2(h12, h13);
            alo[kk][0] = pack_bf16x2(v00 - h00, v01 - h01);
            alo[kk][1] = pack_bf16x2(v10 - h10, v11 - h11);
            alo[kk][2] = pack_bf16x2(v02 - h02, v03 - h03);
            alo[kk][3] = pack_bf16x2(v12 - h12, v13 - h13);
        }

        // ====== GEMM: 8 n-pairs, 6 accumulator chains, depth-1 B prefetch ==
        float oA0 = 0.f, oA1 = 0.f, oA2 = 0.f, oA3 = 0.f;   // point p0
        float oB0 = 0.f, oB1 = 0.f, oB2 = 0.f, oB3 = 0.f;   // point p1
        #pragma unroll 1
        for (int np = 0; np < 8; np++) {
            // c[0]=hh.c0 c[1]=hh.c1 c[2]=lh.c0 c[3]=lh.c1 c[4]=hl.c0 c[5]=hl.c1
            float c0[4] = {0,0,0,0}, c1[4] = {0,0,0,0}, c2[4] = {0,0,0,0};
            float c3[4] = {0,0,0,0}, c4[4] = {0,0,0,0}, c5[4] = {0,0,0,0};
            const uint colb = (uint)np * 32u;
            uint bh[4], bl[4], bhn[4], bln[4];
            ldsm_x4_t(bh[0], bh[1], bh[2], bh[3], bhi_b + colb);
            ldsm_x4_t(bl[0], bl[1], bl[2], bl[3], blo_b + colb);
            #pragma unroll
            for (int kk = 0; kk < 8; kk++) {
                if (kk < 7) {
                    uint ko = colb + (uint)(kk + 1) * (16u * LDB * 2u);
                    ldsm_x4_t(bhn[0], bhn[1], bhn[2], bhn[3], bhi_b + ko);
                    ldsm_x4_t(bln[0], bln[1], bln[2], bln[3], blo_b + ko);
                }
                mma16816(c0, ahi[kk], bh[0], bh[1]);
                mma16816(c1, ahi[kk], bh[2], bh[3]);
                mma16816(c2, alo[kk], bh[0], bh[1]);
                mma16816(c3, alo[kk], bh[2], bh[3]);
                mma16816(c4, ahi[kk], bl[0], bl[1]);
                mma16816(c5, ahi[kk], bl[2], bl[3]);
                if (kk < 7) {
                    #pragma unroll
                    for (int u = 0; u < 4; u++) { bh[u] = bhn[u]; bl[u] = bln[u]; }
                }
            }
            // epilogue: chunk0 cols j0..j0+1 (+rows), chunk1 at +8
            int j0 = np * 16 + lq * 2;
            float2 b2a = *(const float2*)&b2s[j0];
            float2 b2b = *(const float2*)&b2s[j0 + 8];
            float hA0 = fmaxf(c0[0] + c2[0] + c4[0] + b2a.x, 0.f);
            float hA1 = fmaxf(c0[1] + c2[1] + c4[1] + b2a.y, 0.f);
            float hB0 = fmaxf(c0[2] + c2[2] + c4[2] + b2a.x, 0.f);
            float hB1 = fmaxf(c0[3] + c2[3] + c4[3] + b2a.y, 0.f);
            float hA2 = fmaxf(c1[0] + c3[0] + c5[0] + b2b.x, 0.f);
            float hA3 = fmaxf(c1[1] + c3[1] + c5[1] + b2b.y, 0.f);
            float hB2 = fmaxf(c1[2] + c3[2] + c5[2] + b2b.x, 0.f);
            float hB3 = fmaxf(c1[3] + c3[3] + c5[3] + b2b.y, 0.f);

            float4 w0 = *(const float4*)&W3s[j0 * 4];
            float4 w1 = *(const float4*)&W3s[j0 * 4 + 4];
            float4 w2v = *(const float4*)&W3s[(j0 + 8) * 4];
            float4 w3v = *(const float4*)&W3s[(j0 + 8) * 4 + 4];
            oA0 = fmaf(hA0, w0.x, fmaf(hA1, w1.x, fmaf(hA2, w2v.x, fmaf(hA3, w3v.x, oA0))));
            oA1 = fmaf(hA0, w0.y, fmaf(hA1, w1.y, fmaf(hA2, w2v.y, fmaf(hA3, w3v.y, oA1))));
            oA2 = fmaf(hA0, w0.z, fmaf(hA1, w1.z, fmaf(hA2, w2v.z, fmaf(hA3, w3v.z, oA2))));
            oA3 = fmaf(hA0, w0.w, fmaf(hA1, w1.w, fmaf(hA2, w2v.w, fmaf(hA3, w3v.w, oA3))));
            oB0 = fmaf(hB0, w0.x, fmaf(hB1, w1.x, fmaf(hB2, w2v.x, fmaf(hB3, w3v.x, oB0))));
            oB1 = fmaf(hB0, w0.y, fmaf(hB1, w1.y, fmaf(hB2, w2v.y, fmaf(hB3, w3v.y, oB1))));
            oB2 = fmaf(hB0, w0.z, fmaf(hB1, w1.z, fmaf(hB2, w2v.z, fmaf(hB3, w3v.z, oB2))));
            oB3 = fmaf(hB0, w0.w, fmaf(hB1, w1.w, fmaf(hB2, w2v.w, fmaf(hB3, w3v.w, oB3))));
        }

        // reduce partials across the 4 lanes of each quad
        #pragma unroll
        for (int off = 1; off <= 2; off <<= 1) {
            oA0 += __shfl_xor_sync(0xFFFFFFFFu, oA0, off);
            oA1 += __shfl_xor_sync(0xFFFFFFFFu, oA1, off);
            oA2 += __shfl_xor_sync(0xFFFFFFFFu, oA2, off);
            oA3 += __shfl_xor_sync(0xFFFFFFFFu, oA3, off);
            oB0 += __shfl_xor_sync(0xFFFFFFFFu, oB0, off);
            oB1 += __shfl_xor_sync(0xFFFFFFFFu, oB1, off);
            oB2 += __shfl_xor_sync(0xFFFFFFFFu, oB2, off);
            oB3 += __shfl_xor_sync(0xFFFFFFFFu, oB3, off);
        }
        if (lq == 0) {
            outT[p0 * 3 + 0] = oA0 + b3s[0];
            outT[p0 * 3 + 1] = oA1 + b3s[1];
            outT[p0 * 3 + 2] = oA2 + b3s[2];
            outYaw[p0]       = oA3 + b3s[3];
            outT[p1 * 3 + 0] = oB0 + b3s[0];
            outT[p1 * 3 + 1] = oB1 + b3s[1];
            outT[p1 * 3 + 2] = oB2 + b3s[2];
            outYaw[p1]       = oB3 + b3s[3];
        }
    }

    // block-level segment reduction -> global
    __syncthreads();
    if (tid < KSEG * 3) {
        atomicMax(&g_umax[tid], umax[tid]);
        atomicMin(&g_umin[tid], umin[tid]);
    }
}

// ---------------- kernel: flow ---------------------------------------------
__global__ void k_flow(const float* __restrict__ pc1, float* __restrict__ out)
{
    int idx = blockIdx.x * blockDim.x + threadIdx.x;
    if (idx >= NP) return;

    const float* outT   = out + (size_t)33 * NP;
    const float* outYaw = out + (size_t)36 * NP;

    int ind = g_ind[idx];
    float xcx = g_xc[ind*3+0], xcy = g_xc[ind*3+1], xcz = g_xc[ind*3+2];
    float px = pc1[idx*3+0], py = pc1[idx*3+1], pz = pc1[idx*3+2];
    float dx = px - xcx, dy = py - xcy, dz = pz - xcz;

    float yaw = outYaw[idx];
    float c, s; sincosf(yaw, &s, &c);

    float rx = c*dx - s*dy;
    float ry = s*dx + c*dy;

    float tx = outT[idx*3+0], ty = outT[idx*3+1], tz = outT[idx*3+2];

    out[idx*3+0] = (rx + xcx + tx) - px;
    out[idx*3+1] = (ry + xcy + ty) - py;
    out[idx*3+2] = (dz + xcz + tz) - pz;
}

// ---------------- launcher --------------------------------------------------
extern "C" void kernel_launch(void* const* d_in, const int* in_sizes, int n_in,
                              void* d_out, int out_size)
{
    const float* pc1    = (const float*)d_in[0];
    const float* logits = (const float*)d_in[1];
    const float* W1     = (const float*)d_in[2];
    const float* b1     = (const float*)d_in[3];
    const float* W2     = (const float*)d_in[4];
    const float* b2     = (const float*)d_in[5];
    const float* W3     = (const float*)d_in[6];
    const float* b3     = (const float*)d_in[7];
    float* out = (float*)d_out;

    cudaFuncSetAttribute(k_fused, cudaFuncAttributeMaxDynamicSharedMemorySize,
                         SM_TOTAL);

    k_init<<<1, 128>>>();
    k_fused<<<GRID_MMA, 256, SM_TOTAL>>>(pc1, logits, W1, b1, W2, b2, W3, b3, out);
    k_centers<<<1, 128>>>();
    k_flow<<<(NP + 255) / 256, 256>>>(pc1, out);
}

// round 7
// speedup vs baseline: 1.3124x; 1.3124x over previous
#include <cuda_runtime.h>
#include <cuda_fp16.h>
#include <cstdint>

#define NP   1000000
#define KSEG 30
#define H    128

#define WTILES (NP / 16)      // 62500 warp-tiles of 16 points
#define GRID_MMA 304
#define WARPS_PER_BLK 8

typedef unsigned int uint;

// ---------------- scratch (device globals; no allocation allowed) ----------
__device__ unsigned g_umax[KSEG * 3];
__device__ unsigned g_umin[KSEG * 3];
__device__ float    g_xc[KSEG * 3];
__device__ int      g_ind[NP];

__device__ __forceinline__ unsigned fenc(float f) {
    unsigned u = __float_as_uint(f);
    return (u & 0x80000000u) ? ~u : (u | 0x80000000u);
}
__device__ __forceinline__ float fdec(unsigned k) {
    unsigned u = (k & 0x80000000u) ? (k & 0x7FFFFFFFu) : ~k;
    return __uint_as_float(u);
}

// ---------------- small PTX helpers (all baseline features) ----------------
__device__ __forceinline__ uint smem_u32(const void* p) {
    uint a;
    asm("{ .reg .u64 t; cvta.to.shared.u64 t, %1; cvt.u32.u64 %0, t; }"
        : "=r"(a) : "l"(p));
    return a;
}
// pack two fp32 into f16x2: reg.lo = c0, reg.hi = c1
__device__ __forceinline__ uint pack_f16x2(float c0, float c1) {
    uint r;
    asm("cvt.rn.f16x2.f32 %0, %1, %2;" : "=r"(r) : "f"(c1), "f"(c0));
    return r;
}
__device__ __forceinline__ float f16_round(float v) {
    return __half2float(__float2half_rn(v));
}
// x4 trans ldmatrix: lanes 0-15 -> n-chunk c0 rows, lanes 16-31 -> chunk c1
// -> r0,r1 = c0 k0-7,k8-15 ; r2,r3 = c1 k0-7,k8-15
__device__ __forceinline__ void ldsm_x4_t(uint& r0, uint& r1, uint& r2, uint& r3,
                                          uint addr) {
    asm volatile("ldmatrix.sync.aligned.m8n8.x4.trans.shared.b16 {%0,%1,%2,%3}, [%4];"
                 : "=r"(r0), "=r"(r1), "=r"(r2), "=r"(r3) : "r"(addr));
}
__device__ __forceinline__ void mma16816(float* d,
                                         const uint* a,
                                         uint b0, uint b1) {
    asm volatile("mma.sync.aligned.m16n8k16.row.col.f32.f16.f16.f32 "
                 "{%0,%1,%2,%3}, {%4,%5,%6,%7}, {%8,%9}, {%0,%1,%2,%3};"
                 : "+f"(d[0]), "+f"(d[1]), "+f"(d[2]), "+f"(d[3])
                 : "r"(a[0]), "r"(a[1]), "r"(a[2]), "r"(a[3]), "r"(b0), "r"(b1));
}

// ---------------- kernel 0: reset reduction scratch ------------------------
__global__ void k_init() {
    int t = threadIdx.x;
    if (t < KSEG * 3) { g_umax[t] = 0u; g_umin[t] = 0xFFFFFFFFu; }
}

// ---------------- kernel 1: cluster centers (after fused kernel) -----------
__global__ void k_centers() {
    int t = threadIdx.x;
    if (t < KSEG * 3) g_xc[t] = 0.5f * (fdec(g_umax[t]) + fdec(g_umin[t]));
}

// ---------------- fused kernel: softmax+argmax+segmax + MLP (mma.sync) -----
// smem byte layout:
//   [0)      Bf  : 128 x 136 f16  (34816)  row stride 272 B
//   [34816)  W14 : 128 float4 (w1x,w1y,w1z,b1)   (2048)
//   [36864)  b2s : 128 f32   (512)
//   [37376)  W3s : 512 f32   (2048)
//   [39424)  b3s : 4 f32     (16)
//   [39440)  umax: 90 u32    (360)
//   [39800)  umin: 90 u32    (360)
//   [40160)  buf : 8 warps x 496 f32  (15872)   (480 logits + 16 sinv)
#define OFF_BF  0
#define OFF_W14 34816
#define OFF_B2  36864
#define OFF_W3  37376
#define OFF_B3  39424
#define OFF_UMX 39440
#define OFF_UMN 39800
#define OFF_BUF 40160
#define SM_TOTAL 56032
#define LDB 136   // f16 elems per B row

__global__ void __launch_bounds__(256, 2)
k_fused(const float* __restrict__ pc1, const float* __restrict__ logits,
        const float* __restrict__ W1, const float* __restrict__ b1,
        const float* __restrict__ W2, const float* __restrict__ b2,
        const float* __restrict__ W3, const float* __restrict__ b3,
        float* __restrict__ out)
{
    extern __shared__ char smc[];
    __half*   BfS = (__half*)(smc + OFF_BF);
    float4*   W14 = (float4*)(smc + OFF_W14);
    float*    b2s = (float*)(smc + OFF_B2);
    float*    W3s = (float*)(smc + OFF_W3);
    float*    b3s = (float*)(smc + OFF_B3);
    unsigned* umax = (unsigned*)(smc + OFF_UMX);
    unsigned* umin = (unsigned*)(smc + OFF_UMN);

    const int tid = threadIdx.x;

    // one-time weight staging: B = W2 ([k=i][n=j]) in fp16
    for (int x = tid; x < H * H; x += 256) {
        int i = x >> 7, j = x & 127;
        BfS[i * LDB + j] = __float2half_rn(W2[x]);
    }
    if (tid < 128) {
        W14[tid] = make_float4(W1[tid], W1[128 + tid], W1[256 + tid], b1[tid]);
        b2s[tid] = b2[tid];
    }
    for (int i = tid; i < 512; i += 256) W3s[i] = W3[i];
    if (tid < 4) b3s[tid] = b3[tid];
    if (tid < KSEG * 3) { umax[tid] = 0u; umin[tid] = 0xFFFFFFFFu; }
    __syncthreads();

    const int w  = tid >> 5;
    const int l  = tid & 31;
    const int lq = l & 3;     // quad id -> j columns
    const int lr = l >> 2;    // row group -> point rows

    float* wbuf = (float*)(smc + OFF_BUF) + w * 496;
    float* sinv = wbuf + 480;

    // ldmatrix lane base for n-PAIR loads:
    // lanes 0-15 -> chunk 2*np (col byte +0), lanes 16-31 -> chunk 2*np+1 (+16B)
    const uint bf_b = smem_u32(BfS) + (uint)(l & 15) * (LDB * 2)
                    + (uint)((l >> 4) & 1) * 16u;

    float* outMask = out + (size_t)3  * NP;
    float* outT    = out + (size_t)33 * NP;
    float* outYaw  = out + (size_t)36 * NP;

    for (int wt = blockIdx.x * WARPS_PER_BLK + w; wt < WTILES;
         wt += GRID_MMA * WARPS_PER_BLK)
    {
        const int base = wt * 16;

        // ================= softmax + argmax + segment atomics ==============
        __syncwarp();   // protect wbuf/sinv reuse across iterations
        const float* lsrc = logits + (size_t)base * 30;
        #pragma unroll
        for (int r = 0; r < 15; r++) wbuf[r * 32 + l] = lsrc[r * 32 + l];
        __syncwarp();

        {
            int pl = l & 15, hf = l >> 4;
            float* my = wbuf + pl * 30 + hf * 15;
            float bv = my[0]; int bi = 0;
            #pragma unroll
            for (int k = 1; k < 15; k++) {
                float v = my[k];
                if (v > bv) { bv = v; bi = k; }
            }
            bi += hf * 15;
            float bvo = __shfl_xor_sync(0xFFFFFFFFu, bv, 16);
            int   bio = __shfl_xor_sync(0xFFFFFFFFu, bi, 16);
            if (bvo > bv || (bvo == bv && bio < bi)) { bv = bvo; bi = bio; }

            float acc = 0.f;
            #pragma unroll
            for (int k = 0; k < 15; k++) {
                float e = __expf(my[k] - bv);
                my[k] = e; acc += e;
            }
            acc += __shfl_xor_sync(0xFFFFFFFFu, acc, 16);

            if (hf == 0) {
                sinv[pl] = 1.0f / acc;
                int p = base + pl;
                g_ind[p] = bi;
                float qx = pc1[p * 3 + 0];
                float qy = pc1[p * 3 + 1];
                float qz = pc1[p * 3 + 2];
                atomicMax(&umax[bi * 3 + 0], fenc(qx));
                atomicMax(&umax[bi * 3 + 1], fenc(qy));
                atomicMax(&umax[bi * 3 + 2], fenc(qz));
                atomicMin(&umin[bi * 3 + 0], fenc(qx));
                atomicMin(&umin[bi * 3 + 1], fenc(qy));
                atomicMin(&umin[bi * 3 + 2], fenc(qz));
            }
        }
        __syncwarp();

        float* mdst = outMask + (size_t)base * 30;
        #pragma unroll
        for (int r = 0; r < 15; r++) {
            int j = r * 32 + l;
            mdst[j] = wbuf[j] * sinv[(j * 2185) >> 16];   // j/30 exact for j<480
        }

        // ================= layer 1 -> A fragments (hi/lo fp16 split) =======
        const int p0 = base + lr;
        const int p1 = p0 + 8;
        float x0 = pc1[p0 * 3 + 0], y0 = pc1[p0 * 3 + 1], z0 = pc1[p0 * 3 + 2];
        float x1 = pc1[p1 * 3 + 0], y1 = pc1[p1 * 3 + 1], z1 = pc1[p1 * 3 + 2];

        uint ahi[8][4], alo[8][4];
        #pragma unroll
        for (int kk = 0; kk < 8; kk++) {
            int ib = kk * 16 + lq * 2;
            float4 wv0 = W14[ib],     wv1 = W14[ib + 1];
            float4 wv8 = W14[ib + 8], wv9 = W14[ib + 9];
            float v00 = fmaxf(fmaf(x0, wv0.x, fmaf(y0, wv0.y, fmaf(z0, wv0.z, wv0.w))), 0.f);
            float v01 = fmaxf(fmaf(x0, wv1.x, fmaf(y0, wv1.y, fmaf(z0, wv1.z, wv1.w))), 0.f);
            float v02 = fmaxf(fmaf(x0, wv8.x, fmaf(y0, wv8.y, fmaf(z0, wv8.z, wv8.w))), 0.f);
            float v03 = fmaxf(fmaf(x0, wv9.x, fmaf(y0, wv9.y, fmaf(z0, wv9.z, wv9.w))), 0.f);
            float v10 = fmaxf(fmaf(x1, wv0.x, fmaf(y1, wv0.y, fmaf(z1, wv0.z, wv0.w))), 0.f);
            float v11 = fmaxf(fmaf(x1, wv1.x, fmaf(y1, wv1.y, fmaf(z1, wv1.z, wv1.w))), 0.f);
            float v12 = fmaxf(fmaf(x1, wv8.x, fmaf(y1, wv8.y, fmaf(z1, wv8.z, wv8.w))), 0.f);
            float v13 = fmaxf(fmaf(x1, wv9.x, fmaf(y1, wv9.y, fmaf(z1, wv9.z, wv9.w))), 0.f);

            float h00 = f16_round(v00), h01 = f16_round(v01);
            float h02 = f16_round(v02), h03 = f16_round(v03);
            float h10 = f16_round(v10), h11 = f16_round(v11);
            float h12 = f16_round(v12), h13 = f16_round(v13);
            ahi[kk][0] = pack_f16x2(h00, h01);
            ahi[kk][1] = pack_f16x2(h10, h11);
            ahi[kk][2] = pack_f16x2(h02, h03);
            ahi[kk][3] = pack_f16x2(h12, h13);
            alo[kk][0] = pack_f16x2(v00 - h00, v01 - h01);
            alo[kk][1] = pack_f16x2(v10 - h10, v11 - h11);
            alo[kk][2] = pack_f16x2(v02 - h02, v03 - h03);
            alo[kk][3] = pack_f16x2(v12 - h12, v13 - h13);
        }

        // ====== GEMM: 8 n-pairs, 4 accumulator chains (2 terms x 2 chunks) =
        float oA0 = 0.f, oA1 = 0.f, oA2 = 0.f, oA3 = 0.f;   // point p0
        float oB0 = 0.f, oB1 = 0.f, oB2 = 0.f, oB3 = 0.f;   // point p1
        #pragma unroll 1
        for (int np = 0; np < 8; np++) {
            // c0 = hi.chunk0, c1 = hi.chunk1, c2 = lo.chunk0, c3 = lo.chunk1
            float c0[4] = {0,0,0,0}, c1[4] = {0,0,0,0};
            float c2[4] = {0,0,0,0}, c3[4] = {0,0,0,0};
            const uint colb = (uint)np * 32u;
            #pragma unroll
            for (int kk = 0; kk < 8; kk++) {
                uint b0, b1, b2r, b3r;
                ldsm_x4_t(b0, b1, b2r, b3r,
                          bf_b + colb + (uint)kk * (16u * LDB * 2u));
                mma16816(c0, ahi[kk], b0, b1);
                mma16816(c1, ahi[kk], b2r, b3r);
                mma16816(c2, alo[kk], b0, b1);
                mma16816(c3, alo[kk], b2r, b3r);
            }
            // epilogue: chunk0 cols j0..j0+1 (+rows), chunk1 at +8
            int j0 = np * 16 + lq * 2;
            float2 b2a = *(const float2*)&b2s[j0];
            float2 b2b = *(const float2*)&b2s[j0 + 8];
            float hA0 = fmaxf(c0[0] + c2[0] + b2a.x, 0.f);
            float hA1 = fmaxf(c0[1] + c2[1] + b2a.y, 0.f);
            float hB0 = fmaxf(c0[2] + c2[2] + b2a.x, 0.f);
            float hB1 = fmaxf(c0[3] + c2[3] + b2a.y, 0.f);
            float hA2 = fmaxf(c1[0] + c3[0] + b2b.x, 0.f);
            float hA3 = fmaxf(c1[1] + c3[1] + b2b.y, 0.f);
            float hB2 = fmaxf(c1[2] + c3[2] + b2b.x, 0.f);
            float hB3 = fmaxf(c1[3] + c3[3] + b2b.y, 0.f);

            float4 w0 = *(const float4*)&W3s[j0 * 4];
            float4 w1 = *(const float4*)&W3s[j0 * 4 + 4];
            float4 w2v = *(const float4*)&W3s[(j0 + 8) * 4];
            float4 w3v = *(const float4*)&W3s[(j0 + 8) * 4 + 4];
            oA0 = fmaf(hA0, w0.x, fmaf(hA1, w1.x, fmaf(hA2, w2v.x, fmaf(hA3, w3v.x, oA0))));
            oA1 = fmaf(hA0, w0.y, fmaf(hA1, w1.y, fmaf(hA2, w2v.y, fmaf(hA3, w3v.y, oA1))));
            oA2 = fmaf(hA0, w0.z, fmaf(hA1, w1.z, fmaf(hA2, w2v.z, fmaf(hA3, w3v.z, oA2))));
            oA3 = fmaf(hA0, w0.w, fmaf(hA1, w1.w, fmaf(hA2, w2v.w, fmaf(hA3, w3v.w, oA3))));
            oB0 = fmaf(hB0, w0.x, fmaf(hB1, w1.x, fmaf(hB2, w2v.x, fmaf(hB3, w3v.x, oB0))));
            oB1 = fmaf(hB0, w0.y, fmaf(hB1, w1.y, fmaf(hB2, w2v.y, fmaf(hB3, w3v.y, oB1))));
            oB2 = fmaf(hB0, w0.z, fmaf(hB1, w1.z, fmaf(hB2, w2v.z, fmaf(hB3, w3v.z, oB2))));
            oB3 = fmaf(hB0, w0.w, fmaf(hB1, w1.w, fmaf(hB2, w2v.w, fmaf(hB3, w3v.w, oB3))));
        }

        // reduce partials across the 4 lanes of each quad
        #pragma unroll
        for (int off = 1; off <= 2; off <<= 1) {
            oA0 += __shfl_xor_sync(0xFFFFFFFFu, oA0, off);
            oA1 += __shfl_xor_sync(0xFFFFFFFFu, oA1, off);
            oA2 += __shfl_xor_sync(0xFFFFFFFFu, oA2, off);
            oA3 += __shfl_xor_sync(0xFFFFFFFFu, oA3, off);
            oB0 += __shfl_xor_sync(0xFFFFFFFFu, oB0, off);
            oB1 += __shfl_xor_sync(0xFFFFFFFFu, oB1, off);
            oB2 += __shfl_xor_sync(0xFFFFFFFFu, oB2, off);
            oB3 += __shfl_xor_sync(0xFFFFFFFFu, oB3, off);
        }
        if (lq == 0) {
            outT[p0 * 3 + 0] = oA0 + b3s[0];
            outT[p0 * 3 + 1] = oA1 + b3s[1];
            outT[p0 * 3 + 2] = oA2 + b3s[2];
            outYaw[p0]       = oA3 + b3s[3];
            outT[p1 * 3 + 0] = oB0 + b3s[0];
            outT[p1 * 3 + 1] = oB1 + b3s[1];
            outT[p1 * 3 + 2] = oB2 + b3s[2];
            outYaw[p1]       = oB3 + b3s[3];
        }
    }

    // block-level segment reduction -> global
    __syncthreads();
    if (tid < KSEG * 3) {
        atomicMax(&g_umax[tid], umax[tid]);
        atomicMin(&g_umin[tid], umin[tid]);
    }
}

// ---------------- kernel: flow ---------------------------------------------
__global__ void k_flow(const float* __restrict__ pc1, float* __restrict__ out)
{
    int idx = blockIdx.x * blockDim.x + threadIdx.x;
    if (idx >= NP) return;

    const float* outT   = out + (size_t)33 * NP;
    const float* outYaw = out + (size_t)36 * NP;

    int ind = g_ind[idx];
    float xcx = g_xc[ind*3+0], xcy = g_xc[ind*3+1], xcz = g_xc[ind*3+2];
    float px = pc1[idx*3+0], py = pc1[idx*3+1], pz = pc1[idx*3+2];
    float dx = px - xcx, dy = py - xcy, dz = pz - xcz;

    float yaw = outYaw[idx];
    float c, s; sincosf(yaw, &s, &c);

    float rx = c*dx - s*dy;
    float ry = s*dx + c*dy;

    float tx = outT[idx*3+0], ty = outT[idx*3+1], tz = outT[idx*3+2];

    out[idx*3+0] = (rx + xcx + tx) - px;
    out[idx*3+1] = (ry + xcy + ty) - py;
    out[idx*3+2] = (dz + xcz + tz) - pz;
}

// ---------------- launcher --------------------------------------------------
extern "C" void kernel_launch(void* const* d_in, const int* in_sizes, int n_in,
                              void* d_out, int out_size)
{
    const float* pc1    = (const float*)d_in[0];
    const float* logits = (const float*)d_in[1];
    const float* W1     = (const float*)d_in[2];
    const float* b1     = (const float*)d_in[3];
    const float* W2     = (const float*)d_in[4];
    const float* b2     = (const float*)d_in[5];
    const float* W3     = (const float*)d_in[6];
    const float* b3     = (const float*)d_in[7];
    float* out = (float*)d_out;

    cudaFuncSetAttribute(k_fused, cudaFuncAttributeMaxDynamicSharedMemorySize,
                         SM_TOTAL);

    k_init<<<1, 128>>>();
    k_fused<<<GRID_MMA, 256, SM_TOTAL>>>(pc1, logits, W1, b1, W2, b2, W3, b3, out);
    k_centers<<<1, 128>>>();
    k_flow<<<(NP + 255) / 256, 256>>>(pc1, out);
}

// round 9
// speedup vs baseline: 1.3615x; 1.0374x over previous
#include <cuda_runtime.h>
#include <cuda_fp16.h>
#include <cstdint>

#define NP   1000000
#define KSEG 30
#define H    128

#define WTILES2 (NP / 32)     // 31250 tiles of 32 points (2 x 16-pt sub-GEMMs)
#define GRID_MMA 304
#define WARPS_PER_BLK 8
#define STRIDE (GRID_MMA * WARPS_PER_BLK)   // 2432

typedef unsigned int uint;

// ---------------- scratch (device globals; no allocation allowed) ----------
__device__ unsigned g_umax[KSEG * 3];
__device__ unsigned g_umin[KSEG * 3];
__device__ float    g_xc[KSEG * 3];
__device__ int      g_ind[NP];

__device__ __forceinline__ unsigned fenc(float f) {
    unsigned u = __float_as_uint(f);
    return (u & 0x80000000u) ? ~u : (u | 0x80000000u);
}
__device__ __forceinline__ float fdec(unsigned k) {
    unsigned u = (k & 0x80000000u) ? (k & 0x7FFFFFFFu) : ~k;
    return __uint_as_float(u);
}

// ---------------- small PTX helpers (all baseline features) ----------------
__device__ __forceinline__ uint smem_u32(const void* p) {
    uint a;
    asm("{ .reg .u64 t; cvta.to.shared.u64 t, %1; cvt.u32.u64 %0, t; }"
        : "=r"(a) : "l"(p));
    return a;
}
__device__ __forceinline__ uint pack_f16x2(float c0, float c1) {
    uint r;
    asm("cvt.rn.f16x2.f32 %0, %1, %2;" : "=r"(r) : "f"(c1), "f"(c0));
    return r;
}
__device__ __forceinline__ float f16_round(float v) {
    return __half2float(__float2half_rn(v));
}
__device__ __forceinline__ void ldsm_x4_t(uint& r0, uint& r1, uint& r2, uint& r3,
                                          uint addr) {
    asm volatile("ldmatrix.sync.aligned.m8n8.x4.trans.shared.b16 {%0,%1,%2,%3}, [%4];"
                 : "=r"(r0), "=r"(r1), "=r"(r2), "=r"(r3) : "r"(addr));
}
__device__ __forceinline__ void mma16816(float* d, const uint* a,
                                         uint b0, uint b1) {
    asm volatile("mma.sync.aligned.m16n8k16.row.col.f32.f16.f16.f32 "
                 "{%0,%1,%2,%3}, {%4,%5,%6,%7}, {%8,%9}, {%0,%1,%2,%3};"
                 : "+f"(d[0]), "+f"(d[1]), "+f"(d[2]), "+f"(d[3])
                 : "r"(a[0]), "r"(a[1]), "r"(a[2]), "r"(a[3]), "r"(b0), "r"(b1));
}
__device__ __forceinline__ void cp16(uint dst, const void* src) {
    asm volatile("cp.async.cg.shared.global [%0], [%1], 16;"
                 :: "r"(dst), "l"(src));
}
#define CP_COMMIT() asm volatile("cp.async.commit_group;" ::: "memory")
#define CP_WAIT1()  asm volatile("cp.async.wait_group 1;"  ::: "memory")
#define CP_WAIT0()  asm volatile("cp.async.wait_group 0;"  ::: "memory")

// ---------------- kernel 0: reset reduction scratch ------------------------
__global__ void k_init() {
    int t = threadIdx.x;
    if (t < KSEG * 3) { g_umax[t] = 0u; g_umin[t] = 0xFFFFFFFFu; }
}

// ---------------- kernel 1: cluster centers (after fused kernel) -----------
__global__ void k_centers() {
    int t = threadIdx.x;
    if (t < KSEG * 3) g_xc[t] = 0.5f * (fdec(g_umax[t]) + fdec(g_umin[t]));
}

// ---------------- fused kernel ----------------------------------------------
// smem byte layout:
//   [0)      Bf  : 128 x 136 f16  (34816)  row stride 272 B
//   [34816)  W14 : 128 float4 (w1x,w1y,w1z,b1)  (2048)
//   [36864)  b2s : 128 f32  (512)
//   [37376)  W3s : 512 f32  (2048)
//   [39424)  b3s : 4 f32    (16)
//   [39440)  umax: 90 u32   (360)
//   [39800)  umin: 90 u32   (360)
//   [40160)  per-warp buf x 8, 8512 B each:
//            [0)    lbuf: 2 x 960 f32 (7680)   double-buffered logits
//            [7680) pbuf: 2 x 96  f32 (768)    double-buffered pc1
//            [8448) sinv: 16 f32     (64)
#define OFF_BF  0
#define OFF_W14 34816
#define OFF_B2  36864
#define OFF_W3  37376
#define OFF_B3  39424
#define OFF_UMX 39440
#define OFF_UMN 39800
#define OFF_BUF 40160
#define WBUF_SZ 8512
#define SM_TOTAL (OFF_BUF + WARPS_PER_BLK * WBUF_SZ)   // 108256
#define LDB 136   // f16 elems per B row

__global__ void __launch_bounds__(256, 2)
k_fused(const float* __restrict__ pc1, const float* __restrict__ logits,
        const float* __restrict__ W1, const float* __restrict__ b1,
        const float* __restrict__ W2, const float* __restrict__ b2,
        const float* __restrict__ W3, const float* __restrict__ b3,
        float* __restrict__ out)
{
    extern __shared__ char smc[];
    __half*   BfS = (__half*)(smc + OFF_BF);
    float4*   W14 = (float4*)(smc + OFF_W14);
    float*    b2s = (float*)(smc + OFF_B2);
    float*    W3s = (float*)(smc + OFF_W3);
    float*    b3s = (float*)(smc + OFF_B3);
    unsigned* umax = (unsigned*)(smc + OFF_UMX);
    unsigned* umin = (unsigned*)(smc + OFF_UMN);

    const int tid = threadIdx.x;

    // one-time weight staging: B = W2 ([k=i][n=j]) in fp16
    for (int x = tid; x < H * H; x += 256) {
        int i = x >> 7, j = x & 127;
        BfS[i * LDB + j] = __float2half_rn(W2[x]);
    }
    if (tid < 128) {
        W14[tid] = make_float4(W1[tid], W1[128 + tid], W1[256 + tid], b1[tid]);
        b2s[tid] = b2[tid];
    }
    for (int i = tid; i < 512; i += 256) W3s[i] = W3[i];
    if (tid < 4) b3s[tid] = b3[tid];
    if (tid < KSEG * 3) { umax[tid] = 0u; umin[tid] = 0xFFFFFFFFu; }
    __syncthreads();

    const int w  = tid >> 5;
    const int l  = tid & 31;
    const int lq = l & 3;     // quad id -> j columns
    const int lr = l >> 2;    // row group -> point rows

    char* wb = smc + OFF_BUF + w * WBUF_SZ;
    float* lbuf = (float*)wb;            // 2 x 960
    float* pbuf = (float*)(wb + 7680);   // 2 x 96
    float* sinv = (float*)(wb + 8448);   // 16
    const uint lbuf_a = smem_u32(lbuf);
    const uint pbuf_a = smem_u32(pbuf);

    // ldmatrix lane base: lanes 0-15 -> even n-chunk, 16-31 -> odd (+16B)
    const uint bf_b = smem_u32(BfS) + (uint)(l & 15) * (LDB * 2)
                    + (uint)((l >> 4) & 1) * 16u;

    float* outMask = out + (size_t)3  * NP;
    float* outT    = out + (size_t)33 * NP;
    float* outYaw  = out + (size_t)36 * NP;

    // ---- prefetch helper (issue + commit; empty commit if out of range)
    auto prefetch = [&](int bi, int tile) {
        if (tile < WTILES2) {
            const char* ls = (const char*)(logits + (size_t)tile * 960);
            uint ld = lbuf_a + (uint)bi * 3840u;
            #pragma unroll
            for (int i = 0; i < 7; i++) {
                int idx = i * 32 + l;
                cp16(ld + (uint)idx * 16u, ls + idx * 16);
            }
            if (l < 16) cp16(ld + (uint)(224 + l) * 16u, ls + (224 + l) * 16);
            const char* ps = (const char*)(pc1 + (size_t)tile * 96);
            if (l < 24) cp16(pbuf_a + (uint)bi * 384u + (uint)l * 16u,
                             ps + l * 16);
        }
        CP_COMMIT();
    };

    int wt0 = blockIdx.x * WARPS_PER_BLK + w;
    prefetch(0, wt0);

    int ii = 0;
    for (int wt = wt0; wt < WTILES2; wt += STRIDE, ii++) {
        const int cur = ii & 1;
        const int base = wt * 32;

        __syncwarp();                    // prior iter done reading buf cur^1
        prefetch(cur ^ 1, wt + STRIDE);
        CP_WAIT1();                      // buffer cur ready
        __syncwarp();

        float* lb = lbuf + cur * 960;
        float* pb = pbuf + cur * 96;

        // ============== softmax + argmax + segment atomics (2 passes) ======
        #pragma unroll
        for (int sp = 0; sp < 2; sp++) {
            int pl = l & 15, hf = l >> 4;
            float* my = lb + sp * 480 + pl * 30 + hf * 15;
            float bv = my[0]; int bi = 0;
            #pragma unroll
            for (int k = 1; k < 15; k++) {
                float v = my[k];
                if (v > bv) { bv = v; bi = k; }
            }
            bi += hf * 15;
            float bvo = __shfl_xor_sync(0xFFFFFFFFu, bv, 16);
            int   bio = __shfl_xor_sync(0xFFFFFFFFu, bi, 16);
            if (bvo > bv || (bvo == bv && bio < bi)) { bv = bvo; bi = bio; }

            float acc = 0.f;
            #pragma unroll
            for (int k = 0; k < 15; k++) {
                float e = __expf(my[k] - bv);
                my[k] = e; acc += e;
            }
            acc += __shfl_xor_sync(0xFFFFFFFFu, acc, 16);

            if (hf == 0) {
                sinv[pl] = 1.0f / acc;
                int p = base + sp * 16 + pl;
                g_ind[p] = bi;
                int q = sp * 16 + pl;
                float qx = pb[q * 3 + 0];
                float qy = pb[q * 3 + 1];
                float qz = pb[q * 3 + 2];
                atomicMax(&umax[bi * 3 + 0], fenc(qx));
                atomicMax(&umax[bi * 3 + 1], fenc(qy));
                atomicMax(&umax[bi * 3 + 2], fenc(qz));
                atomicMin(&umin[bi * 3 + 0], fenc(qx));
                atomicMin(&umin[bi * 3 + 1], fenc(qy));
                atomicMin(&umin[bi * 3 + 2], fenc(qz));
            }
            __syncwarp();

            float* mdst = outMask + (size_t)(base + sp * 16) * 30;
            float* le = lb + sp * 480;
            #pragma unroll
            for (int r = 0; r < 15; r++) {
                int j = r * 32 + l;
                mdst[j] = le[j] * sinv[(j * 2185) >> 16];
            }
            __syncwarp();
        }

        // ===== 2 sub-tiles of 16 points: A-split fp16 GEMM (R7 numerics) ===
        #pragma unroll 1
        for (int st = 0; st < 2; st++) {
            const float* pq = pb + st * 48;
            const int pbase = base + st * 16;
            const int p0 = pbase + lr;
            const int p1 = p0 + 8;
            float x0 = pq[lr * 3 + 0],       y0 = pq[lr * 3 + 1],       z0 = pq[lr * 3 + 2];
            float x1 = pq[(lr + 8) * 3 + 0], y1 = pq[(lr + 8) * 3 + 1], z1 = pq[(lr + 8) * 3 + 2];

            // ---- layer 1 -> A fragments (hi/lo fp16 split)
            uint ahi[8][4], alo[8][4];
            #pragma unroll
            for (int kk = 0; kk < 8; kk++) {
                int ib = kk * 16 + lq * 2;
                float4 wv0 = W14[ib],     wv1 = W14[ib + 1];
                float4 wv8 = W14[ib + 8], wv9 = W14[ib + 9];
                float v00 = fmaxf(fmaf(x0, wv0.x, fmaf(y0, wv0.y, fmaf(z0, wv0.z, wv0.w))), 0.f);
                float v01 = fmaxf(fmaf(x0, wv1.x, fmaf(y0, wv1.y, fmaf(z0, wv1.z, wv1.w))), 0.f);
                float v02 = fmaxf(fmaf(x0, wv8.x, fmaf(y0, wv8.y, fmaf(z0, wv8.z, wv8.w))), 0.f);
                float v03 = fmaxf(fmaf(x0, wv9.x, fmaf(y0, wv9.y, fmaf(z0, wv9.z, wv9.w))), 0.f);
                float v10 = fmaxf(fmaf(x1, wv0.x, fmaf(y1, wv0.y, fmaf(z1, wv0.z, wv0.w))), 0.f);
                float v11 = fmaxf(fmaf(x1, wv1.x, fmaf(y1, wv1.y, fmaf(z1, wv1.z, wv1.w))), 0.f);
                float v12 = fmaxf(fmaf(x1, wv8.x, fmaf(y1, wv8.y, fmaf(z1, wv8.z, wv8.w))), 0.f);
                float v13 = fmaxf(fmaf(x1, wv9.x, fmaf(y1, wv9.y, fmaf(z1, wv9.z, wv9.w))), 0.f);

                float h00 = f16_round(v00), h01 = f16_round(v01);
                float h02 = f16_round(v02), h03 = f16_round(v03);
                float h10 = f16_round(v10), h11 = f16_round(v11);
                float h12 = f16_round(v12), h13 = f16_round(v13);
                ahi[kk][0] = pack_f16x2(h00, h01);
                ahi[kk][1] = pack_f16x2(h10, h11);
                ahi[kk][2] = pack_f16x2(h02, h03);
                ahi[kk][3] = pack_f16x2(h12, h13);
                alo[kk][0] = pack_f16x2(v00 - h00, v01 - h01);
                alo[kk][1] = pack_f16x2(v10 - h10, v11 - h11);
                alo[kk][2] = pack_f16x2(v02 - h02, v03 - h03);
                alo[kk][3] = pack_f16x2(v12 - h12, v13 - h13);
            }

            // ---- GEMM: 8 n-pairs, 4 chains (hi/lo x 2 chunks)
            float oA0 = 0.f, oA1 = 0.f, oA2 = 0.f, oA3 = 0.f;   // point p0
            float oB0 = 0.f, oB1 = 0.f, oB2 = 0.f, oB3 = 0.f;   // point p1
            #pragma unroll 1
            for (int np = 0; np < 8; np++) {
                float c0[4] = {0,0,0,0}, c1[4] = {0,0,0,0};
                float c2[4] = {0,0,0,0}, c3[4] = {0,0,0,0};
                const uint colb = (uint)np * 32u;
                #pragma unroll
                for (int kk = 0; kk < 8; kk++) {
                    uint b0, b1r, b2r, b3r;
                    ldsm_x4_t(b0, b1r, b2r, b3r,
                              bf_b + colb + (uint)kk * (16u * LDB * 2u));
                    mma16816(c0, ahi[kk], b0, b1r);
                    mma16816(c1, ahi[kk], b2r, b3r);
                    mma16816(c2, alo[kk], b0, b1r);
                    mma16816(c3, alo[kk], b2r, b3r);
                }
                int j0 = np * 16 + lq * 2;
                float2 b2a = *(const float2*)&b2s[j0];
                float2 b2b = *(const float2*)&b2s[j0 + 8];
                float hA0 = fmaxf(c0[0] + c2[0] + b2a.x, 0.f);
                float hA1 = fmaxf(c0[1] + c2[1] + b2a.y, 0.f);
                float hB0 = fmaxf(c0[2] + c2[2] + b2a.x, 0.f);
                float hB1 = fmaxf(c0[3] + c2[3] + b2a.y, 0.f);
                float hA2 = fmaxf(c1[0] + c3[0] + b2b.x, 0.f);
                float hA3 = fmaxf(c1[1] + c3[1] + b2b.y, 0.f);
                float hB2 = fmaxf(c1[2] + c3[2] + b2b.x, 0.f);
                float hB3 = fmaxf(c1[3] + c3[3] + b2b.y, 0.f);

                float4 w0 = *(const float4*)&W3s[j0 * 4];
                float4 w1 = *(const float4*)&W3s[j0 * 4 + 4];
                float4 w2v = *(const float4*)&W3s[(j0 + 8) * 4];
                float4 w3v = *(const float4*)&W3s[(j0 + 8) * 4 + 4];
                oA0 = fmaf(hA0, w0.x, fmaf(hA1, w1.x, fmaf(hA2, w2v.x, fmaf(hA3, w3v.x, oA0))));
                oA1 = fmaf(hA0, w0.y, fmaf(hA1, w1.y, fmaf(hA2, w2v.y, fmaf(hA3, w3v.y, oA1))));
                oA2 = fmaf(hA0, w0.z, fmaf(hA1, w1.z, fmaf(hA2, w2v.z, fmaf(hA3, w3v.z, oA2))));
                oA3 = fmaf(hA0, w0.w, fmaf(hA1, w1.w, fmaf(hA2, w2v.w, fmaf(hA3, w3v.w, oA3))));
                oB0 = fmaf(hB0, w0.x, fmaf(hB1, w1.x, fmaf(hB2, w2v.x, fmaf(hB3, w3v.x, oB0))));
                oB1 = fmaf(hB0, w0.y, fmaf(hB1, w1.y, fmaf(hB2, w2v.y, fmaf(hB3, w3v.y, oB1))));
                oB2 = fmaf(hB0, w0.z, fmaf(hB1, w1.z, fmaf(hB2, w2v.z, fmaf(hB3, w3v.z, oB2))));
                oB3 = fmaf(hB0, w0.w, fmaf(hB1, w1.w, fmaf(hB2, w2v.w, fmaf(hB3, w3v.w, oB3))));
            }

            // reduce partials across the 4 lanes of each quad
            #pragma unroll
            for (int off = 1; off <= 2; off <<= 1) {
                oA0 += __shfl_xor_sync(0xFFFFFFFFu, oA0, off);
                oA1 += __shfl_xor_sync(0xFFFFFFFFu, oA1, off);
                oA2 += __shfl_xor_sync(0xFFFFFFFFu, oA2, off);
                oA3 += __shfl_xor_sync(0xFFFFFFFFu, oA3, off);
                oB0 += __shfl_xor_sync(0xFFFFFFFFu, oB0, off);
                oB1 += __shfl_xor_sync(0xFFFFFFFFu, oB1, off);
                oB2 += __shfl_xor_sync(0xFFFFFFFFu, oB2, off);
                oB3 += __shfl_xor_sync(0xFFFFFFFFu, oB3, off);
            }
            if (lq == 0) {
                outT[p0 * 3 + 0] = oA0 + b3s[0];
                outT[p0 * 3 + 1] = oA1 + b3s[1];
                outT[p0 * 3 + 2] = oA2 + b3s[2];
                outYaw[p0]       = oA3 + b3s[3];
                outT[p1 * 3 + 0] = oB0 + b3s[0];
                outT[p1 * 3 + 1] = oB1 + b3s[1];
                outT[p1 * 3 + 2] = oB2 + b3s[2];
                outYaw[p1]       = oB3 + b3s[3];
            }
        }
    }

    CP_WAIT0();   // drain any pending prefetch before exit

    // block-level segment reduction -> global
    __syncthreads();
    if (tid < KSEG * 3) {
        atomicMax(&g_umax[tid], umax[tid]);
        atomicMin(&g_umin[tid], umin[tid]);
    }
}

// ---------------- kernel: flow ---------------------------------------------
__global__ void k_flow(const float* __restrict__ pc1, float* __restrict__ out)
{
    int idx = blockIdx.x * blockDim.x + threadIdx.x;
    if (idx >= NP) return;

    const float* outT   = out + (size_t)33 * NP;
    const float* outYaw = out + (size_t)36 * NP;

    int ind = g_ind[idx];
    float xcx = g_xc[ind*3+0], xcy = g_xc[ind*3+1], xcz = g_xc[ind*3+2];
    float px = pc1[idx*3+0], py = pc1[idx*3+1], pz = pc1[idx*3+2];
    float dx = px - xcx, dy = py - xcy, dz = pz - xcz;

    float yaw = outYaw[idx];
    float c, s; sincosf(yaw, &s, &c);

    float rx = c*dx - s*dy;
    float ry = s*dx + c*dy;

    float tx = outT[idx*3+0], ty = outT[idx*3+1], tz = outT[idx*3+2];

    out[idx*3+0] = (rx + xcx + tx) - px;
    out[idx*3+1] = (ry + xcy + ty) - py;
    out[idx*3+2] = (dz + xcz + tz) - pz;
}

// ---------------- launcher --------------------------------------------------
extern "C" void kernel_launch(void* const* d_in, const int* in_sizes, int n_in,
                              void* d_out, int out_size)
{
    const float* pc1    = (const float*)d_in[0];
    const float* logits = (const float*)d_in[1];
    const float* W1     = (const float*)d_in[2];
    const float* b1     = (const float*)d_in[3];
    const float* W2     = (const float*)d_in[4];
    const float* b2     = (const float*)d_in[5];
    const float* W3     = (const float*)d_in[6];
    const float* b3     = (const float*)d_in[7];
    float* out = (float*)d_out;

    cudaFuncSetAttribute(k_fused, cudaFuncAttributeMaxDynamicSharedMemorySize,
                         SM_TOTAL);

    k_init<<<1, 128>>>();
    k_fused<<<GRID_MMA, 256, SM_TOTAL>>>(pc1, logits, W1, b1, W2, b2, W3, b3, out);
    k_centers<<<1, 128>>>();
    k_flow<<<(NP + 255) / 256, 256>>>(pc1, out);
}